// round 4
// baseline (speedup 1.0000x reference)
#include <cuda_runtime.h>
#include <math.h>

#define BATCH 2
#define HDIM 256
#define WDIM 256
#define CDIM 512
#define KM 64
#define NBLK 8
#define BSZ 64
#define HID 128
#define N1 131072          /* WDIM*CDIM */
#define PTOT 8192          /* BATCH*KM*KM */

// ---------------- scratch (device globals: no allocation allowed) ----------
__device__ float g_cosT[256];
__device__ float g_sinT[256];
__device__ float g_Yr[(size_t)BATCH * KM * N1];
__device__ float g_Yi[(size_t)BATCH * KM * N1];
__device__ float g_Zr[(size_t)BATCH * KM * KM * CDIM];
__device__ float g_Zi[(size_t)BATCH * KM * KM * CDIM];
__device__ float g_Hr[(size_t)NBLK * PTOT * HID];
__device__ float g_Hi[(size_t)NBLK * PTOT * HID];
__device__ float g_Or[(size_t)BATCH * KM * KM * CDIM];
__device__ float g_Oi[(size_t)BATCH * KM * KM * CDIM];
__device__ float g_Ur[(size_t)BATCH * KM * N1];
__device__ float g_Ui[(size_t)BATCH * KM * N1];

__device__ __forceinline__ float gelu_f(float v) {
    return 0.5f * v * (1.0f + erff(v * 0.70710678118654752440f));
}

__global__ void k_init_tab() {
    int t = threadIdx.x;
    g_cosT[t] = cospif((float)t * (1.0f / 128.0f));
    g_sinT[t] = sinpif((float)t * (1.0f / 128.0f));
}

// ---------------------------------------------------------------------------
// Stage 1: h-DFT (truncated): Y[b,ky,wc] = (1/16) * sum_h e^{-2pi i ky h/256} x[b,h,wc]
// ---------------------------------------------------------------------------
__global__ __launch_bounds__(256) void k_s1(const float* __restrict__ x) {
    __shared__ float xs[16][64];
    __shared__ float mc[64][16];
    __shared__ float ms[64][16];
    const int b = blockIdx.y;
    const int col0 = blockIdx.x * 64;
    const int tid = threadIdx.x;
    const int tx = tid & 15, ty = tid >> 4;
    float ar[4][4] = {};
    float ai[4][4] = {};
    const float* xb = x + (size_t)b * HDIM * N1 + col0;
    for (int h0 = 0; h0 < HDIM; h0 += 16) {
        *(float4*)&xs[ty][tx * 4] =
            *(const float4*)(xb + (size_t)(h0 + ty) * N1 + tx * 4);
#pragma unroll
        for (int q = 0; q < 4; q++) {
            int ee = tid * 4 + q;
            int ky = ee >> 4, hh = ee & 15;
            int t = (ky * (h0 + hh)) & 255;
            mc[ky][hh] = g_cosT[t];
            ms[ky][hh] = g_sinT[t];
        }
        __syncthreads();
#pragma unroll
        for (int hh = 0; hh < 16; hh++) {
            float4 xv = *(float4*)&xs[hh][tx * 4];
#pragma unroll
            for (int j = 0; j < 4; j++) {
                float cv = mc[ty + 16 * j][hh];
                float sv = ms[ty + 16 * j][hh];
                ar[j][0] += cv * xv.x; ar[j][1] += cv * xv.y;
                ar[j][2] += cv * xv.z; ar[j][3] += cv * xv.w;
                ai[j][0] -= sv * xv.x; ai[j][1] -= sv * xv.y;
                ai[j][2] -= sv * xv.z; ai[j][3] -= sv * xv.w;
            }
        }
        __syncthreads();
    }
#pragma unroll
    for (int j = 0; j < 4; j++) {
        int ky = ty + 16 * j;
        size_t o = ((size_t)(b * KM + ky)) * N1 + col0 + tx * 4;
        float4 vr = make_float4(ar[j][0] * 0.0625f, ar[j][1] * 0.0625f,
                                ar[j][2] * 0.0625f, ar[j][3] * 0.0625f);
        float4 vi = make_float4(ai[j][0] * 0.0625f, ai[j][1] * 0.0625f,
                                ai[j][2] * 0.0625f, ai[j][3] * 0.0625f);
        *(float4*)(g_Yr + o) = vr;
        *(float4*)(g_Yi + o) = vi;
    }
}

// ---------------------------------------------------------------------------
// Stage 2: w-DFT: Z[b,ky,kx,c] = (1/16) sum_w e^{-2pi i kx w/256} Y[b,ky,w,c]
//   Zr = (1/16) sum (c*Yr + s*Yi),  Zi = (1/16) sum (c*Yi - s*Yr)
// ---------------------------------------------------------------------------
__global__ __launch_bounds__(256) void k_s2() {
    __shared__ float yr_s[16][64];
    __shared__ float yi_s[16][64];
    __shared__ float mc[64][16];
    __shared__ float ms[64][16];
    const int b = blockIdx.z, ky = blockIdx.y, c0 = blockIdx.x * 64;
    const size_t base = ((size_t)(b * KM + ky)) * N1;
    const int tid = threadIdx.x;
    const int tx = tid & 15, ty = tid >> 4;
    float zr[4][4] = {};
    float zi[4][4] = {};
    for (int w0 = 0; w0 < WDIM; w0 += 16) {
        size_t yidx = base + (size_t)(w0 + ty) * CDIM + c0 + tx * 4;
        *(float4*)&yr_s[ty][tx * 4] = *(const float4*)(g_Yr + yidx);
        *(float4*)&yi_s[ty][tx * 4] = *(const float4*)(g_Yi + yidx);
#pragma unroll
        for (int q = 0; q < 4; q++) {
            int ee = tid * 4 + q;
            int kx = ee >> 4, ww = ee & 15;
            int t = (kx * (w0 + ww)) & 255;
            mc[kx][ww] = g_cosT[t];
            ms[kx][ww] = g_sinT[t];
        }
        __syncthreads();
#pragma unroll
        for (int ww = 0; ww < 16; ww++) {
            float4 yr4 = *(float4*)&yr_s[ww][tx * 4];
            float4 yi4 = *(float4*)&yi_s[ww][tx * 4];
#pragma unroll
            for (int j = 0; j < 4; j++) {
                float cv = mc[ty + 16 * j][ww];
                float sv = ms[ty + 16 * j][ww];
                zr[j][0] += cv * yr4.x + sv * yi4.x;
                zr[j][1] += cv * yr4.y + sv * yi4.y;
                zr[j][2] += cv * yr4.z + sv * yi4.z;
                zr[j][3] += cv * yr4.w + sv * yi4.w;
                zi[j][0] += cv * yi4.x - sv * yr4.x;
                zi[j][1] += cv * yi4.y - sv * yr4.y;
                zi[j][2] += cv * yi4.z - sv * yr4.z;
                zi[j][3] += cv * yi4.w - sv * yr4.w;
            }
        }
        __syncthreads();
    }
#pragma unroll
    for (int j = 0; j < 4; j++) {
        int kx = ty + 16 * j;
        size_t o = ((size_t)((b * KM + ky) * KM + kx)) * CDIM + c0 + tx * 4;
        float4 vr = make_float4(zr[j][0] * 0.0625f, zr[j][1] * 0.0625f,
                                zr[j][2] * 0.0625f, zr[j][3] * 0.0625f);
        float4 vi = make_float4(zi[j][0] * 0.0625f, zi[j][1] * 0.0625f,
                                zi[j][2] * 0.0625f, zi[j][3] * 0.0625f);
        *(float4*)(g_Zr + o) = vr;
        *(float4*)(g_Zi + o) = vi;
    }
}

// ---------------------------------------------------------------------------
// Stage 3a: H = gelu(Z @ W1 + b1)  (complex, per block n)
// ---------------------------------------------------------------------------
__global__ __launch_bounds__(256) void k_s3a(const float* __restrict__ pw1,
                                             const float* __restrict__ pb1) {
    __shared__ float zr_s[64][16];
    __shared__ float zi_s[64][16];
    __shared__ float wa_s[16][64];
    __shared__ float wb_s[16][64];
    const int n = blockIdx.z, o0 = blockIdx.y * 64, p0 = blockIdx.x * 64;
    const int tid = threadIdx.x;
    const int tx = tid & 15, ty = tid >> 4;
    float hr[4][4] = {};
    float hi[4][4] = {};
    for (int i0 = 0; i0 < BSZ; i0 += 16) {
        {
            int p = tid >> 2, i4 = (tid & 3) * 4;
            size_t zidx = (size_t)(p0 + p) * CDIM + n * BSZ + i0 + i4;
            *(float4*)&zr_s[p][i4] = *(const float4*)(g_Zr + zidx);
            *(float4*)&zi_s[p][i4] = *(const float4*)(g_Zi + zidx);
        }
        {
            int ii = tid >> 4, o4 = (tid & 15) * 4;
            size_t widx = ((size_t)(n * BSZ + i0 + ii)) * HID + o0 + o4;
            *(float4*)&wa_s[ii][o4] = *(const float4*)(pw1 + widx);
            *(float4*)&wb_s[ii][o4] =
                *(const float4*)(pw1 + (size_t)NBLK * BSZ * HID + widx);
        }
        __syncthreads();
#pragma unroll
        for (int ii = 0; ii < 16; ii++) {
            float4 a = *(float4*)&wa_s[ii][tx * 4];
            float4 c = *(float4*)&wb_s[ii][tx * 4];
#pragma unroll
            for (int j = 0; j < 4; j++) {
                float zrv = zr_s[ty + 16 * j][ii];
                float ziv = zi_s[ty + 16 * j][ii];
                hr[j][0] += zrv * a.x - ziv * c.x;
                hr[j][1] += zrv * a.y - ziv * c.y;
                hr[j][2] += zrv * a.z - ziv * c.z;
                hr[j][3] += zrv * a.w - ziv * c.w;
                hi[j][0] += ziv * a.x + zrv * c.x;
                hi[j][1] += ziv * a.y + zrv * c.y;
                hi[j][2] += ziv * a.z + zrv * c.z;
                hi[j][3] += ziv * a.w + zrv * c.w;
            }
        }
        __syncthreads();
    }
    float4 br = *(const float4*)(pb1 + (size_t)n * HID + o0 + tx * 4);
    float4 bi = *(const float4*)(pb1 + (size_t)NBLK * HID + (size_t)n * HID + o0 + tx * 4);
#pragma unroll
    for (int j = 0; j < 4; j++) {
        int p = p0 + ty + 16 * j;
        size_t o = ((size_t)n * PTOT + p) * HID + o0 + tx * 4;
        float4 vr = make_float4(gelu_f(hr[j][0] + br.x), gelu_f(hr[j][1] + br.y),
                                gelu_f(hr[j][2] + br.z), gelu_f(hr[j][3] + br.w));
        float4 vi = make_float4(gelu_f(hi[j][0] + bi.x), gelu_f(hi[j][1] + bi.y),
                                gelu_f(hi[j][2] + bi.z), gelu_f(hi[j][3] + bi.w));
        *(float4*)(g_Hr + o) = vr;
        *(float4*)(g_Hi + o) = vi;
    }
}

// ---------------------------------------------------------------------------
// Stage 3b: O = H @ W2 + b2  (complex, per block n)
// ---------------------------------------------------------------------------
__global__ __launch_bounds__(256) void k_s3b(const float* __restrict__ pw2,
                                             const float* __restrict__ pb2) {
    __shared__ float hr_s[64][16];
    __shared__ float hi_s[64][16];
    __shared__ float wa_s[16][64];
    __shared__ float wb_s[16][64];
    const int n = blockIdx.z, p0 = blockIdx.x * 64;
    const int tid = threadIdx.x;
    const int tx = tid & 15, ty = tid >> 4;
    float orr[4][4] = {};
    float oii[4][4] = {};
    for (int i0 = 0; i0 < HID; i0 += 16) {
        {
            int p = tid >> 2, i4 = (tid & 3) * 4;
            size_t hidx = ((size_t)n * PTOT + p0 + p) * HID + i0 + i4;
            *(float4*)&hr_s[p][i4] = *(const float4*)(g_Hr + hidx);
            *(float4*)&hi_s[p][i4] = *(const float4*)(g_Hi + hidx);
        }
        {
            int ii = tid >> 4, o4 = (tid & 15) * 4;
            size_t widx = ((size_t)(n * HID + i0 + ii)) * BSZ + o4;
            *(float4*)&wa_s[ii][o4] = *(const float4*)(pw2 + widx);
            *(float4*)&wb_s[ii][o4] =
                *(const float4*)(pw2 + (size_t)NBLK * HID * BSZ + widx);
        }
        __syncthreads();
#pragma unroll
        for (int ii = 0; ii < 16; ii++) {
            float4 a = *(float4*)&wa_s[ii][tx * 4];
            float4 c = *(float4*)&wb_s[ii][tx * 4];
#pragma unroll
            for (int j = 0; j < 4; j++) {
                float hrv = hr_s[ty + 16 * j][ii];
                float hiv = hi_s[ty + 16 * j][ii];
                orr[j][0] += hrv * a.x - hiv * c.x;
                orr[j][1] += hrv * a.y - hiv * c.y;
                orr[j][2] += hrv * a.z - hiv * c.z;
                orr[j][3] += hrv * a.w - hiv * c.w;
                oii[j][0] += hiv * a.x + hrv * c.x;
                oii[j][1] += hiv * a.y + hrv * c.y;
                oii[j][2] += hiv * a.z + hrv * c.z;
                oii[j][3] += hiv * a.w + hrv * c.w;
            }
        }
        __syncthreads();
    }
    float4 br = *(const float4*)(pb2 + (size_t)n * BSZ + tx * 4);
    float4 bi = *(const float4*)(pb2 + (size_t)NBLK * BSZ + (size_t)n * BSZ + tx * 4);
#pragma unroll
    for (int j = 0; j < 4; j++) {
        int p = p0 + ty + 16 * j;
        size_t o = (size_t)p * CDIM + n * BSZ + tx * 4;
        float4 vr = make_float4(orr[j][0] + br.x, orr[j][1] + br.y,
                                orr[j][2] + br.z, orr[j][3] + br.w);
        float4 vi = make_float4(oii[j][0] + bi.x, oii[j][1] + bi.y,
                                oii[j][2] + bi.z, oii[j][3] + bi.w);
        *(float4*)(g_Or + o) = vr;
        *(float4*)(g_Oi + o) = vi;
    }
}

// ---------------------------------------------------------------------------
// Stage 4: inverse-w: U[b,ky,w,c] = (1/16) sum_kx d(kx) e^{+2pi i kx w/256} O[b,ky,kx,c]
//   Ur = sum d*(c*Or - s*Oi),  Ui = sum d*(s*Or + c*Oi)
// ---------------------------------------------------------------------------
__global__ __launch_bounds__(256) void k_s4() {
    __shared__ float or_s[16][64];
    __shared__ float oi_s[16][64];
    __shared__ float mc[64][16];
    __shared__ float ms[64][16];
    const int bky = blockIdx.z;
    const int w0 = blockIdx.y * 64, c0 = blockIdx.x * 64;
    const int tid = threadIdx.x;
    const int tx = tid & 15, ty = tid >> 4;
    float ur[4][4] = {};
    float ui[4][4] = {};
    for (int k0 = 0; k0 < KM; k0 += 16) {
        {
            int kk = ty, c4 = tx * 4;
            size_t oidx = ((size_t)bky * KM + k0 + kk) * CDIM + c0 + c4;
            float d = (k0 + kk == 0) ? 1.0f : 2.0f;
            float4 a = *(const float4*)(g_Or + oidx);
            float4 c = *(const float4*)(g_Oi + oidx);
            a.x *= d; a.y *= d; a.z *= d; a.w *= d;
            c.x *= d; c.y *= d; c.z *= d; c.w *= d;
            *(float4*)&or_s[kk][c4] = a;
            *(float4*)&oi_s[kk][c4] = c;
        }
#pragma unroll
        for (int q = 0; q < 4; q++) {
            int ee = tid * 4 + q;
            int ww = ee >> 4, kk = ee & 15;
            int t = ((k0 + kk) * (w0 + ww)) & 255;
            mc[ww][kk] = g_cosT[t];
            ms[ww][kk] = g_sinT[t];
        }
        __syncthreads();
#pragma unroll
        for (int kk = 0; kk < 16; kk++) {
            float4 a = *(float4*)&or_s[kk][tx * 4];
            float4 c = *(float4*)&oi_s[kk][tx * 4];
#pragma unroll
            for (int j = 0; j < 4; j++) {
                float cv = mc[ty + 16 * j][kk];
                float sv = ms[ty + 16 * j][kk];
                ur[j][0] += cv * a.x - sv * c.x;
                ur[j][1] += cv * a.y - sv * c.y;
                ur[j][2] += cv * a.z - sv * c.z;
                ur[j][3] += cv * a.w - sv * c.w;
                ui[j][0] += sv * a.x + cv * c.x;
                ui[j][1] += sv * a.y + cv * c.y;
                ui[j][2] += sv * a.z + cv * c.z;
                ui[j][3] += sv * a.w + cv * c.w;
            }
        }
        __syncthreads();
    }
#pragma unroll
    for (int j = 0; j < 4; j++) {
        int wl = w0 + ty + 16 * j;
        size_t o = (size_t)bky * N1 + (size_t)wl * CDIM + c0 + tx * 4;
        float4 vr = make_float4(ur[j][0] * 0.0625f, ur[j][1] * 0.0625f,
                                ur[j][2] * 0.0625f, ur[j][3] * 0.0625f);
        float4 vi = make_float4(ui[j][0] * 0.0625f, ui[j][1] * 0.0625f,
                                ui[j][2] * 0.0625f, ui[j][3] * 0.0625f);
        *(float4*)(g_Ur + o) = vr;
        *(float4*)(g_Ui + o) = vi;
    }
}

// ---------------------------------------------------------------------------
// Stage 5: inverse-h + Re + residual:
//   out[b,h,wc] = x[b,h,wc] + (1/16) sum_ky (c(ky*h)*Ur - s(ky*h)*Ui)
// ---------------------------------------------------------------------------
__global__ __launch_bounds__(256) void k_s5(const float* __restrict__ x,
                                            float* __restrict__ out) {
    __shared__ float ur_s[16][64];
    __shared__ float ui_s[16][64];
    __shared__ float mc[64][16];
    __shared__ float ms[64][16];
    const int b = blockIdx.z, h0 = blockIdx.y * 64, col0 = blockIdx.x * 64;
    const int tid = threadIdx.x;
    const int tx = tid & 15, ty = tid >> 4;
    float acc[4][4] = {};
    for (int k0 = 0; k0 < KM; k0 += 16) {
        {
            int kk = ty, c4 = tx * 4;
            size_t uidx = ((size_t)(b * KM + k0 + kk)) * N1 + col0 + c4;
            *(float4*)&ur_s[kk][c4] = *(const float4*)(g_Ur + uidx);
            *(float4*)&ui_s[kk][c4] = *(const float4*)(g_Ui + uidx);
        }
#pragma unroll
        for (int q = 0; q < 4; q++) {
            int ee = tid * 4 + q;
            int hl = ee >> 4, kk = ee & 15;
            int t = ((k0 + kk) * (h0 + hl)) & 255;
            mc[hl][kk] = g_cosT[t];
            ms[hl][kk] = g_sinT[t];
        }
        __syncthreads();
#pragma unroll
        for (int kk = 0; kk < 16; kk++) {
            float4 a = *(float4*)&ur_s[kk][tx * 4];
            float4 c = *(float4*)&ui_s[kk][tx * 4];
#pragma unroll
            for (int j = 0; j < 4; j++) {
                float cv = mc[ty + 16 * j][kk];
                float sv = ms[ty + 16 * j][kk];
                acc[j][0] += cv * a.x - sv * c.x;
                acc[j][1] += cv * a.y - sv * c.y;
                acc[j][2] += cv * a.z - sv * c.z;
                acc[j][3] += cv * a.w - sv * c.w;
            }
        }
        __syncthreads();
    }
#pragma unroll
    for (int j = 0; j < 4; j++) {
        int h = h0 + ty + 16 * j;
        size_t oidx = ((size_t)(b * HDIM + h)) * N1 + col0 + tx * 4;
        float4 xv = *(const float4*)(x + oidx);
        float4 v = make_float4(xv.x + acc[j][0] * 0.0625f,
                               xv.y + acc[j][1] * 0.0625f,
                               xv.z + acc[j][2] * 0.0625f,
                               xv.w + acc[j][3] * 0.0625f);
        *(float4*)(out + oidx) = v;
    }
}

// ---------------------------------------------------------------------------
extern "C" void kernel_launch(void* const* d_in, const int* in_sizes, int n_in,
                              void* d_out, int out_size) {
    const float* x = (const float*)d_in[0];
    const float* w1 = (const float*)d_in[1];
    const float* b1 = (const float*)d_in[2];
    const float* w2 = (const float*)d_in[3];
    const float* b2 = (const float*)d_in[4];
    float* out = (float*)d_out;

    k_init_tab<<<1, 256>>>();
    k_s1<<<dim3(N1 / 64, BATCH), 256>>>(x);
    k_s2<<<dim3(CDIM / 64, KM, BATCH), 256>>>();
    k_s3a<<<dim3(PTOT / 64, HID / 64, NBLK), 256>>>(w1, b1);
    k_s3b<<<dim3(PTOT / 64, 1, NBLK), 256>>>(w2, b2);
    k_s4<<<dim3(CDIM / 64, WDIM / 64, BATCH * KM), 256>>>();
    k_s5<<<dim3(N1 / 64, HDIM / 64, BATCH), 256>>>(x, out);
}

// round 5
// speedup vs baseline: 3.3444x; 3.3444x over previous
#include <cuda_runtime.h>
#include <cuda_bf16.h>
#include <math.h>

#define BATCH 2
#define HDIM 256
#define WDIM 256
#define CDIM 512
#define KM 64
#define NBLK 8
#define N1 131072          /* WDIM*CDIM */

// ---------------- scratch (device globals; uint4 for 16B alignment) --------
__device__ uint4 g_A1_4[128 * 256 / 8];
__device__ uint4 g_A2_4[128 * 512 / 8];
__device__ uint4 g_A4_4[512 * 128 / 8];
__device__ uint4 g_A5_4[256 * 128 / 8];
__device__ uint4 g_B3_4[8 * 128 * 256 / 8];
__device__ uint4 g_B4_4[8 * 256 * 128 / 8];
__device__ float g_b3f[8 * 256];
__device__ float g_b4f[8 * 128];
__device__ uint4 g_Y_4[(size_t)2 * 128 * N1 / 8];   // [b][ri*64+ky][w*512+c]
__device__ uint4 g_Z_4[(size_t)8192 * 1024 / 8];    // [p][n*128 + ri*64 + c64]
__device__ uint4 g_H_4[(size_t)8192 * 2048 / 8];    // [p][n*256 + o2]
__device__ uint4 g_O_4[(size_t)16384 * 512 / 8];    // [((b64ky)*2+ri)*64+kx][c]
__device__ uint4 g_U_4[(size_t)2 * 128 * N1 / 8];   // [b][ri*64+ky][w*512+c]

#define g_A1 ((__nv_bfloat16*)g_A1_4)
#define g_A2 ((__nv_bfloat16*)g_A2_4)
#define g_A4 ((__nv_bfloat16*)g_A4_4)
#define g_A5 ((__nv_bfloat16*)g_A5_4)
#define g_B3 ((__nv_bfloat16*)g_B3_4)
#define g_B4 ((__nv_bfloat16*)g_B4_4)
#define g_Y  ((__nv_bfloat16*)g_Y_4)
#define g_Z  ((__nv_bfloat16*)g_Z_4)
#define g_H  ((__nv_bfloat16*)g_H_4)
#define g_O  ((__nv_bfloat16*)g_O_4)
#define g_U  ((__nv_bfloat16*)g_U_4)

// ---------------------------------------------------------------------------
__device__ __forceinline__ float gelu_f(float v) {
    return 0.5f * v * (1.0f + erff(v * 0.70710678118654752440f));
}
__device__ __forceinline__ unsigned pack_bf16(float a, float b) {
    unsigned lo = __bfloat16_as_ushort(__float2bfloat16(a));
    unsigned hi = __bfloat16_as_ushort(__float2bfloat16(b));
    return lo | (hi << 16);
}
__device__ __forceinline__ void mma16816(float* d, const unsigned* a, const unsigned* b) {
    asm volatile(
        "mma.sync.aligned.m16n8k16.row.col.f32.bf16.bf16.f32 "
        "{%0,%1,%2,%3}, {%4,%5,%6,%7}, {%8,%9}, {%0,%1,%2,%3};\n"
        : "+f"(d[0]), "+f"(d[1]), "+f"(d[2]), "+f"(d[3])
        : "r"(a[0]), "r"(a[1]), "r"(a[2]), "r"(a[3]), "r"(b[0]), "r"(b[1]));
}

// ---- tile loaders ---------------------------------------------------------
// A tile: 128 rows x 64 bf16, row-major copy into As[128][72]
__device__ __forceinline__ void lda_tile(const __nv_bfloat16* __restrict__ src,
                                         size_t stride, __nv_bfloat16 (*As)[72], int tid) {
    int r = tid >> 1, c0 = (tid & 1) << 5;
    const uint4* p = (const uint4*)(src + (size_t)r * stride + c0);
    uint4 q0 = p[0], q1 = p[1], q2 = p[2], q3 = p[3];
    uint4* d = (uint4*)&As[r][c0];
    d[0] = q0; d[1] = q1; d[2] = q2; d[3] = q3;
}
// B tile: 64 k-rows x 64 n-cols (k-major source), transposed into Bt[n][k]
__device__ __forceinline__ void ldb_tile_bf16(const __nv_bfloat16* __restrict__ src,
                                              size_t stride, __nv_bfloat16 (*Bt)[72], int tid) {
    int kr = tid >> 2, nc0 = (tid & 3) << 4;
    const uint4* p = (const uint4*)(src + (size_t)kr * stride + nc0);
    uint4 q0 = p[0], q1 = p[1];
    __nv_bfloat16 t[16];
    *(uint4*)t = q0; *(uint4*)(t + 8) = q1;
#pragma unroll
    for (int j = 0; j < 16; j++) Bt[nc0 + j][kr] = t[j];
}
__device__ __forceinline__ void ldb_tile_f32(const float* __restrict__ src,
                                             size_t stride, __nv_bfloat16 (*Bt)[72], int tid) {
    int kr = tid >> 2, nc0 = (tid & 3) << 4;
    const float4* p = (const float4*)(src + (size_t)kr * stride + nc0);
#pragma unroll
    for (int jj = 0; jj < 4; jj++) {
        float4 v = p[jj];
        Bt[nc0 + jj * 4 + 0][kr] = __float2bfloat16(v.x);
        Bt[nc0 + jj * 4 + 1][kr] = __float2bfloat16(v.y);
        Bt[nc0 + jj * 4 + 2][kr] = __float2bfloat16(v.z);
        Bt[nc0 + jj * 4 + 3][kr] = __float2bfloat16(v.w);
    }
}
// core: one 64-deep K tile of the 128x64 block, 8 warps of 32x32
__device__ __forceinline__ void compute_tile(const __nv_bfloat16 (*As)[72],
                                             const __nv_bfloat16 (*Bt)[72],
                                             float acc[2][4][4], int lane, int wm, int wn) {
#pragma unroll
    for (int kk = 0; kk < 4; kk++) {
        unsigned a[2][4], b[4][2];
        int c2 = kk * 16 + ((lane & 3) << 1);
#pragma unroll
        for (int fm = 0; fm < 2; fm++) {
            int r0 = wm * 32 + fm * 16 + (lane >> 2);
            a[fm][0] = *(const unsigned*)&As[r0][c2];
            a[fm][1] = *(const unsigned*)&As[r0 + 8][c2];
            a[fm][2] = *(const unsigned*)&As[r0][c2 + 8];
            a[fm][3] = *(const unsigned*)&As[r0 + 8][c2 + 8];
        }
#pragma unroll
        for (int fn = 0; fn < 4; fn++) {
            int nr = wn * 32 + fn * 8 + (lane >> 2);
            b[fn][0] = *(const unsigned*)&Bt[nr][c2];
            b[fn][1] = *(const unsigned*)&Bt[nr][c2 + 8];
        }
#pragma unroll
        for (int fm = 0; fm < 2; fm++)
#pragma unroll
            for (int fn = 0; fn < 4; fn++) mma16816(acc[fm][fn], a[fm], b[fn]);
    }
}

#define GEMM_PROLOG                                                     \
    __shared__ __nv_bfloat16 As[128][72];                               \
    __shared__ __nv_bfloat16 Bt[64][72];                                \
    const int tid = threadIdx.x, lane = tid & 31;                       \
    const int wm = (tid >> 5) >> 1, wn = (tid >> 5) & 1;                \
    float acc[2][4][4] = {};

// ---------------------------------------------------------------------------
// prep: DFT A-matrices
__global__ void k_prep_dft() {
    int id = blockIdx.x * 256 + threadIdx.x;
    const float inv128 = 1.0f / 128.0f;
    if (id < 32768) {                         // A1 [128][256]
        int m = id >> 8, h = id & 255;
        float v = (m < 64) ? cospif(((m * h) & 255) * inv128)
                           : -sinpif((((m - 64) * h) & 255) * inv128);
        g_A1[id] = __float2bfloat16(v * 0.0625f);
    } else if (id < 98304) {                  // A2 [128][512]
        int t = id - 32768, m = t >> 9, k = t & 511;
        float v;
        if (m < 64) v = (k < 256) ? cospif(((m * k) & 255) * inv128)
                                  : sinpif(((m * (k - 256)) & 255) * inv128);
        else {
            int mm = m - 64;
            v = (k < 256) ? -sinpif(((mm * k) & 255) * inv128)
                          : cospif(((mm * (k - 256)) & 255) * inv128);
        }
        g_A2[t] = __float2bfloat16(v * 0.0625f);
    } else if (id < 163840) {                 // A4 [512][128]
        int t = id - 98304, m = t >> 7, k = t & 127;
        int kx = k & 63, w = m & 255;
        float d = (kx == 0) ? 0.0625f : 0.125f;
        float ang = ((kx * w) & 255) * inv128;
        float v;
        if (m < 256) v = (k < 64) ? cospif(ang) : -sinpif(ang);
        else         v = (k < 64) ? sinpif(ang) : cospif(ang);
        g_A4[t] = __float2bfloat16(v * d);
    } else if (id < 196608) {                 // A5 [256][128]
        int t = id - 163840, h = t >> 7, k = t & 127;
        int ky = k & 63;
        float ang = ((ky * h) & 255) * inv128;
        float v = (k < 64) ? cospif(ang) : -sinpif(ang);
        g_A5[t] = __float2bfloat16(v * 0.0625f);
    }
}
// prep: MLP weight matrices (complex -> stacked real form)
__global__ void k_prep_w(const float* __restrict__ w1, const float* __restrict__ b1,
                         const float* __restrict__ w2, const float* __restrict__ b2) {
    int id = blockIdx.x * 256 + threadIdx.x;
    if (id < 262144) {                         // B3 [8][128][256]
        int n = id >> 15, r = id & 32767, k = r >> 8, o = r & 255;
        float v;
        if (k < 64)
            v = (o < 128) ? w1[((size_t)n * 64 + k) * 128 + o]
                          : w1[((size_t)(8 + n) * 64 + k) * 128 + (o - 128)];
        else {
            int kk = k - 64;
            v = (o < 128) ? -w1[((size_t)(8 + n) * 64 + kk) * 128 + o]
                          : w1[((size_t)n * 64 + kk) * 128 + (o - 128)];
        }
        g_B3[id] = __float2bfloat16(v);
    } else if (id < 524288) {                  // B4 [8][256][128]
        int t = id - 262144, n = t >> 15, r = t & 32767, k = r >> 7, o = r & 127;
        float v;
        if (k < 128)
            v = (o < 64) ? w2[((size_t)n * 128 + k) * 64 + o]
                         : w2[((size_t)(8 + n) * 128 + k) * 64 + (o - 64)];
        else {
            int kk = k - 128;
            v = (o < 64) ? -w2[((size_t)(8 + n) * 128 + kk) * 64 + o]
                         : w2[((size_t)n * 128 + kk) * 64 + (o - 64)];
        }
        g_B4[t] = __float2bfloat16(v);
    } else if (id < 526336) {                  // b3f [8][256]
        int t = id - 524288, n = t >> 8, o = t & 255;
        g_b3f[t] = (o < 128) ? b1[n * 128 + o] : b1[1024 + n * 128 + (o - 128)];
    } else if (id < 527360) {                  // b4f [8][128]
        int t = id - 526336, n = t >> 7, o = t & 127;
        g_b4f[t] = (o < 64) ? b2[n * 64 + o] : b2[512 + n * 64 + (o - 64)];
    }
}

// ---------------------------------------------------------------------------
// S1: Y[b][m=ri*64+ky][wc] = A1 @ x   (m16n8k16 block GEMM)
__global__ __launch_bounds__(256) void k_s1(const float* __restrict__ x) {
    GEMM_PROLOG
    const int col0 = blockIdx.x * 64, b = blockIdx.y;
    const float* xb = x + (size_t)b * HDIM * N1;
    for (int kt = 0; kt < 4; kt++) {
        lda_tile(g_A1 + kt * 64, 256, As, tid);
        ldb_tile_f32(xb + (size_t)(kt * 64) * N1 + col0, N1, Bt, tid);
        __syncthreads();
        compute_tile(As, Bt, acc, lane, wm, wn);
        __syncthreads();
    }
    size_t base = ((size_t)b * 128) * N1 + col0;
#pragma unroll
    for (int fm = 0; fm < 2; fm++)
#pragma unroll
        for (int fn = 0; fn < 4; fn++) {
            int m = wm * 32 + fm * 16 + (lane >> 2);
            int col = wn * 32 + fn * 8 + ((lane & 3) << 1);
            const float* d = acc[fm][fn];
#pragma unroll
            for (int hh = 0; hh < 2; hh++) {
                size_t idx = base + (size_t)(m + hh * 8) * N1 + col;
                *(unsigned*)&g_Y[idx] = pack_bf16(d[hh * 2], d[hh * 2 + 1]);
            }
        }
}

// S2: per slab (b,ky): Z = A2 @ [Yr;Yi]
__global__ __launch_bounds__(256) void k_s2() {
    GEMM_PROLOG
    const int bx = blockIdx.x, slab = blockIdx.y;
    const int b = slab >> 6, ky = slab & 63;
    const int c0 = bx * 64;
    for (int kt = 0; kt < 8; kt++) {
        lda_tile(g_A2 + kt * 64, 512, As, tid);
        int ri = kt >> 2, w0 = (kt & 3) * 64;
        ldb_tile_bf16(g_Y + ((size_t)b * 128 + ri * 64 + ky) * N1 + (size_t)w0 * 512 + c0,
                      512, Bt, tid);
        __syncthreads();
        compute_tile(As, Bt, acc, lane, wm, wn);
        __syncthreads();
    }
    size_t pbase = (size_t)slab * 64;
#pragma unroll
    for (int fm = 0; fm < 2; fm++)
#pragma unroll
        for (int fn = 0; fn < 4; fn++) {
            int m = wm * 32 + fm * 16 + (lane >> 2);
            int col = wn * 32 + fn * 8 + ((lane & 3) << 1);
            const float* d = acc[fm][fn];
#pragma unroll
            for (int hh = 0; hh < 2; hh++) {
                int mm = m + hh * 8;
                int ri = mm >> 6, kx = mm & 63;
                size_t idx = (pbase + kx) * 1024 + (size_t)bx * 128 + ri * 64 + col;
                *(unsigned*)&g_Z[idx] = pack_bf16(d[hh * 2], d[hh * 2 + 1]);
            }
        }
}

// S3a: H = gelu(Z @ B3 + b3)
__global__ __launch_bounds__(256) void k_s3a() {
    GEMM_PROLOG
    const int p0 = blockIdx.x * 128, o0 = blockIdx.y * 64, n = blockIdx.z;
    for (int kt = 0; kt < 2; kt++) {
        lda_tile(g_Z + (size_t)p0 * 1024 + n * 128 + kt * 64, 1024, As, tid);
        ldb_tile_bf16(g_B3 + ((size_t)n * 128 + kt * 64) * 256 + o0, 256, Bt, tid);
        __syncthreads();
        compute_tile(As, Bt, acc, lane, wm, wn);
        __syncthreads();
    }
#pragma unroll
    for (int fm = 0; fm < 2; fm++)
#pragma unroll
        for (int fn = 0; fn < 4; fn++) {
            int m = wm * 32 + fm * 16 + (lane >> 2);
            int o2 = o0 + wn * 32 + fn * 8 + ((lane & 3) << 1);
            float2 bv = *(const float2*)&g_b3f[n * 256 + o2];
            const float* d = acc[fm][fn];
#pragma unroll
            for (int hh = 0; hh < 2; hh++) {
                int p = p0 + m + hh * 8;
                size_t idx = (size_t)p * 2048 + n * 256 + o2;
                *(unsigned*)&g_H[idx] =
                    pack_bf16(gelu_f(d[hh * 2] + bv.x), gelu_f(d[hh * 2 + 1] + bv.y));
            }
        }
}

// S3b: O = H @ B4 + b4
__global__ __launch_bounds__(256) void k_s3b() {
    GEMM_PROLOG
    const int p0 = blockIdx.x * 128, o0 = blockIdx.y * 64, n = blockIdx.z;
    for (int kt = 0; kt < 4; kt++) {
        lda_tile(g_H + (size_t)p0 * 2048 + n * 256 + kt * 64, 2048, As, tid);
        ldb_tile_bf16(g_B4 + ((size_t)n * 256 + kt * 64) * 128 + o0, 128, Bt, tid);
        __syncthreads();
        compute_tile(As, Bt, acc, lane, wm, wn);
        __syncthreads();
    }
#pragma unroll
    for (int fm = 0; fm < 2; fm++)
#pragma unroll
        for (int fn = 0; fn < 4; fn++) {
            int m = wm * 32 + fm * 16 + (lane >> 2);
            int o2 = o0 + wn * 32 + fn * 8 + ((lane & 3) << 1);
            float2 bv = *(const float2*)&g_b4f[n * 128 + o2];
            int ri = o2 >> 6, c = n * 64 + (o2 & 63);
            const float* d = acc[fm][fn];
#pragma unroll
            for (int hh = 0; hh < 2; hh++) {
                int p = p0 + m + hh * 8;
                int b = p >> 12, ky = (p >> 6) & 63, kx = p & 63;
                size_t idx = (((size_t)(b * 64 + ky) * 2 + ri) * 64 + kx) * 512 + c;
                *(unsigned*)&g_O[idx] =
                    pack_bf16(d[hh * 2] + bv.x, d[hh * 2 + 1] + bv.y);
            }
        }
}

// S4: per slab: [Ur;Ui] = A4 @ [Or;Oi]
__global__ __launch_bounds__(256) void k_s4() {
    GEMM_PROLOG
    const int c0 = blockIdx.x * 64, m0 = blockIdx.y * 128, slab = blockIdx.z;
    const int b = slab >> 6, ky = slab & 63;
    for (int kt = 0; kt < 2; kt++) {
        lda_tile(g_A4 + (size_t)m0 * 128 + kt * 64, 128, As, tid);
        ldb_tile_bf16(g_O + ((size_t)(slab * 2 + kt)) * 64 * 512 + c0, 512, Bt, tid);
        __syncthreads();
        compute_tile(As, Bt, acc, lane, wm, wn);
        __syncthreads();
    }
#pragma unroll
    for (int fm = 0; fm < 2; fm++)
#pragma unroll
        for (int fn = 0; fn < 4; fn++) {
            int m = wm * 32 + fm * 16 + (lane >> 2);
            int c = c0 + wn * 32 + fn * 8 + ((lane & 3) << 1);
            const float* d = acc[fm][fn];
#pragma unroll
            for (int hh = 0; hh < 2; hh++) {
                int mg = m0 + m + hh * 8;
                size_t row, w;
                if (mg < 256) { row = (size_t)b * 128 + ky;      w = mg; }
                else          { row = (size_t)b * 128 + 64 + ky; w = mg - 256; }
                size_t idx = row * N1 + w * 512 + c;
                *(unsigned*)&g_U[idx] = pack_bf16(d[hh * 2], d[hh * 2 + 1]);
            }
        }
}

// S5: out = x + A5 @ [Ur;Ui]
__global__ __launch_bounds__(256) void k_s5(const float* __restrict__ x,
                                            float* __restrict__ out) {
    GEMM_PROLOG
    const int col0 = blockIdx.x * 64, m0 = blockIdx.y * 128, b = blockIdx.z;
    for (int kt = 0; kt < 2; kt++) {
        lda_tile(g_A5 + (size_t)m0 * 128 + kt * 64, 128, As, tid);
        ldb_tile_bf16(g_U + ((size_t)b * 128 + kt * 64) * N1 + col0, N1, Bt, tid);
        __syncthreads();
        compute_tile(As, Bt, acc, lane, wm, wn);
        __syncthreads();
    }
#pragma unroll
    for (int fm = 0; fm < 2; fm++)
#pragma unroll
        for (int fn = 0; fn < 4; fn++) {
            int m = wm * 32 + fm * 16 + (lane >> 2);
            int col = wn * 32 + fn * 8 + ((lane & 3) << 1);
            const float* d = acc[fm][fn];
#pragma unroll
            for (int hh = 0; hh < 2; hh++) {
                int h = m0 + m + hh * 8;
                size_t idx = ((size_t)b * HDIM + h) * N1 + col0 + col;
                float2 xv = *(const float2*)&x[idx];
                float2 o;
                o.x = xv.x + d[hh * 2];
                o.y = xv.y + d[hh * 2 + 1];
                *(float2*)&out[idx] = o;
            }
        }
}

// ---------------------------------------------------------------------------
extern "C" void kernel_launch(void* const* d_in, const int* in_sizes, int n_in,
                              void* d_out, int out_size) {
    const float* x  = (const float*)d_in[0];
    const float* w1 = (const float*)d_in[1];
    const float* b1 = (const float*)d_in[2];
    const float* w2 = (const float*)d_in[3];
    const float* b2 = (const float*)d_in[4];
    float* out = (float*)d_out;

    k_prep_dft<<<768, 256>>>();
    k_prep_w<<<2060, 256>>>(w1, b1, w2, b2);
    k_s1<<<dim3(N1 / 64, BATCH), 256>>>(x);
    k_s2<<<dim3(8, BATCH * KM), 256>>>();
    k_s3a<<<dim3(64, 4, NBLK), 256>>>();
    k_s3b<<<dim3(64, 2, NBLK), 256>>>();
    k_s4<<<dim3(8, 4, BATCH * KM), 256>>>();
    k_s5<<<dim3(N1 / 64, 2, BATCH), 256>>>(x, out);
}

// round 6
// speedup vs baseline: 3.8477x; 1.1505x over previous
#include <cuda_runtime.h>
#include <cuda_bf16.h>
#include <math.h>

#define BATCH 2
#define HDIM 256
#define WDIM 256
#define CDIM 512
#define KM 64
#define NBLK 8
#define N1 131072          /* WDIM*CDIM */

// ---------------- scratch (device globals; uint4 for 16B alignment) --------
__device__ uint4 g_A1_4[128 * 256 / 8];
__device__ uint4 g_A2_4[128 * 512 / 8];
__device__ uint4 g_A4_4[512 * 128 / 8];
__device__ uint4 g_A5_4[256 * 128 / 8];
__device__ uint4 g_B3_4[8 * 128 * 256 / 8];
__device__ uint4 g_B4_4[8 * 256 * 128 / 8];
__device__ float g_b3f[8 * 256];
__device__ float g_b4f[8 * 128];
__device__ uint4 g_Y_4[(size_t)2 * 128 * N1 / 8];   // [b][ri*64+ky][w*512+c]
__device__ uint4 g_Z_4[(size_t)8192 * 1024 / 8];    // [p][n*128 + ri*64 + c64]
__device__ uint4 g_H_4[(size_t)8192 * 2048 / 8];    // [p][n*256 + o2]
__device__ uint4 g_O_4[(size_t)16384 * 512 / 8];    // [((b64ky)*2+ri)*64+kx][c]
__device__ uint4 g_U_4[(size_t)2 * 128 * N1 / 8];   // [b][ri*64+ky][w*512+c]

#define g_A1 ((__nv_bfloat16*)g_A1_4)
#define g_A2 ((__nv_bfloat16*)g_A2_4)
#define g_A4 ((__nv_bfloat16*)g_A4_4)
#define g_A5 ((__nv_bfloat16*)g_A5_4)
#define g_B3 ((__nv_bfloat16*)g_B3_4)
#define g_B4 ((__nv_bfloat16*)g_B4_4)
#define g_Y  ((__nv_bfloat16*)g_Y_4)
#define g_Z  ((__nv_bfloat16*)g_Z_4)
#define g_H  ((__nv_bfloat16*)g_H_4)
#define g_O  ((__nv_bfloat16*)g_O_4)
#define g_U  ((__nv_bfloat16*)g_U_4)

// ---------------------------------------------------------------------------
__device__ __forceinline__ float gelu_f(float v) {
    return 0.5f * v * (1.0f + erff(v * 0.70710678118654752440f));
}
__device__ __forceinline__ unsigned pack_bf16(float a, float b) {
    unsigned lo = __bfloat16_as_ushort(__float2bfloat16(a));
    unsigned hi = __bfloat16_as_ushort(__float2bfloat16(b));
    return lo | (hi << 16);
}
__device__ __forceinline__ void mma16816(float* d, const unsigned* a, const unsigned* b) {
    asm volatile(
        "mma.sync.aligned.m16n8k16.row.col.f32.bf16.bf16.f32 "
        "{%0,%1,%2,%3}, {%4,%5,%6,%7}, {%8,%9}, {%0,%1,%2,%3};\n"
        : "+f"(d[0]), "+f"(d[1]), "+f"(d[2]), "+f"(d[3])
        : "r"(a[0]), "r"(a[1]), "r"(a[2]), "r"(a[3]), "r"(b[0]), "r"(b[1]));
}

// ---- tile loaders ---------------------------------------------------------
// A tile: 128 rows x 64 bf16, row-major copy into As[128][72]
__device__ __forceinline__ void lda_tile(const __nv_bfloat16* __restrict__ src,
                                         size_t stride, __nv_bfloat16 (*As)[72], int tid) {
    int r = tid >> 1, c0 = (tid & 1) << 5;
    const uint4* p = (const uint4*)(src + (size_t)r * stride + c0);
    uint4 q0 = p[0], q1 = p[1], q2 = p[2], q3 = p[3];
    uint4* d = (uint4*)&As[r][c0];
    d[0] = q0; d[1] = q1; d[2] = q2; d[3] = q3;
}
// B tile: 64 k-rows x 64 n-cols, kept K-MAJOR in SMEM (vectorized, no transpose)
__device__ __forceinline__ void ldb_tile_bf16(const __nv_bfloat16* __restrict__ src,
                                              size_t stride, __nv_bfloat16 (*Bs)[72], int tid) {
    int r = tid >> 2, c0 = (tid & 3) << 4;
    const uint4* p = (const uint4*)(src + (size_t)r * stride + c0);
    uint4 q0 = p[0], q1 = p[1];
    uint4* d = (uint4*)&Bs[r][c0];
    d[0] = q0; d[1] = q1;
}
__device__ __forceinline__ void ldb_tile_f32(const float* __restrict__ src,
                                             size_t stride, __nv_bfloat16 (*Bs)[72], int tid) {
    int r = tid >> 2, c0 = (tid & 3) << 4;
    const float4* p = (const float4*)(src + (size_t)r * stride + c0);
#pragma unroll
    for (int h = 0; h < 2; h++) {
        float4 v0 = p[h * 2], v1 = p[h * 2 + 1];
        uint4 o;
        o.x = pack_bf16(v0.x, v0.y); o.y = pack_bf16(v0.z, v0.w);
        o.z = pack_bf16(v1.x, v1.y); o.w = pack_bf16(v1.z, v1.w);
        *(uint4*)&Bs[r][c0 + h * 8] = o;
    }
}
// core: one 64-deep K tile of the 128x64 block, 8 warps of 32x32, ldmatrix path
__device__ __forceinline__ void compute_tile(const __nv_bfloat16 (*As)[72],
                                             const __nv_bfloat16 (*Bs)[72],
                                             float acc[2][4][4], int lane, int wm, int wn) {
    const int r8 = lane & 7, q = lane >> 3;
#pragma unroll
    for (int kk = 0; kk < 4; kk++) {
        const int k0 = kk * 16;
        unsigned a[2][4], b[4][2];
#pragma unroll
        for (int fm = 0; fm < 2; fm++) {
            int row = wm * 32 + fm * 16 + (q & 1) * 8 + r8;
            int col = k0 + (q >> 1) * 8;
            unsigned addr = (unsigned)__cvta_generic_to_shared(&As[row][col]);
            asm volatile("ldmatrix.sync.aligned.m8n8.x4.shared.b16 {%0,%1,%2,%3}, [%4];\n"
                         : "=r"(a[fm][0]), "=r"(a[fm][1]), "=r"(a[fm][2]), "=r"(a[fm][3])
                         : "r"(addr));
        }
#pragma unroll
        for (int fn2 = 0; fn2 < 2; fn2++) {
            int krow = k0 + (q & 1) * 8 + r8;
            int ncol = wn * 32 + fn2 * 16 + (q >> 1) * 8;
            unsigned addr = (unsigned)__cvta_generic_to_shared(&Bs[krow][ncol]);
            asm volatile("ldmatrix.sync.aligned.m8n8.x4.trans.shared.b16 {%0,%1,%2,%3}, [%4];\n"
                         : "=r"(b[fn2 * 2][0]), "=r"(b[fn2 * 2][1]),
                           "=r"(b[fn2 * 2 + 1][0]), "=r"(b[fn2 * 2 + 1][1])
                         : "r"(addr));
        }
#pragma unroll
        for (int fm = 0; fm < 2; fm++)
#pragma unroll
            for (int fn = 0; fn < 4; fn++) mma16816(acc[fm][fn], a[fm], b[fn]);
    }
}

#define GEMM_PROLOG                                                     \
    __shared__ __nv_bfloat16 As[128][72];                               \
    __shared__ __nv_bfloat16 Bs[64][72];                                \
    const int tid = threadIdx.x, lane = tid & 31;                       \
    const int wm = (tid >> 5) >> 1, wn = (tid >> 5) & 1;                \
    float acc[2][4][4] = {};

// ---------------------------------------------------------------------------
// prep: DFT A-matrices
__global__ void k_prep_dft() {
    int id = blockIdx.x * 256 + threadIdx.x;
    const float inv128 = 1.0f / 128.0f;
    if (id < 32768) {                         // A1 [128][256]
        int m = id >> 8, h = id & 255;
        float v = (m < 64) ? cospif(((m * h) & 255) * inv128)
                           : -sinpif((((m - 64) * h) & 255) * inv128);
        g_A1[id] = __float2bfloat16(v * 0.0625f);
    } else if (id < 98304) {                  // A2 [128][512]
        int t = id - 32768, m = t >> 9, k = t & 511;
        float v;
        if (m < 64) v = (k < 256) ? cospif(((m * k) & 255) * inv128)
                                  : sinpif(((m * (k - 256)) & 255) * inv128);
        else {
            int mm = m - 64;
            v = (k < 256) ? -sinpif(((mm * k) & 255) * inv128)
                          : cospif(((mm * (k - 256)) & 255) * inv128);
        }
        g_A2[t] = __float2bfloat16(v * 0.0625f);
    } else if (id < 163840) {                 // A4 [512][128]
        int t = id - 98304, m = t >> 7, k = t & 127;
        int kx = k & 63, w = m & 255;
        float d = (kx == 0) ? 0.0625f : 0.125f;
        float ang = ((kx * w) & 255) * inv128;
        float v;
        if (m < 256) v = (k < 64) ? cospif(ang) : -sinpif(ang);
        else         v = (k < 64) ? sinpif(ang) : cospif(ang);
        g_A4[t] = __float2bfloat16(v * d);
    } else if (id < 196608) {                 // A5 [256][128]
        int t = id - 163840, h = t >> 7, k = t & 127;
        int ky = k & 63;
        float ang = ((ky * h) & 255) * inv128;
        float v = (k < 64) ? cospif(ang) : -sinpif(ang);
        g_A5[t] = __float2bfloat16(v * 0.0625f);
    }
}
// prep: MLP weight matrices (complex -> stacked real form)
__global__ void k_prep_w(const float* __restrict__ w1, const float* __restrict__ b1,
                         const float* __restrict__ w2, const float* __restrict__ b2) {
    int id = blockIdx.x * 256 + threadIdx.x;
    if (id < 262144) {                         // B3 [8][128][256]
        int n = id >> 15, r = id & 32767, k = r >> 8, o = r & 255;
        float v;
        if (k < 64)
            v = (o < 128) ? w1[((size_t)n * 64 + k) * 128 + o]
                          : w1[((size_t)(8 + n) * 64 + k) * 128 + (o - 128)];
        else {
            int kk = k - 64;
            v = (o < 128) ? -w1[((size_t)(8 + n) * 64 + kk) * 128 + o]
                          : w1[((size_t)n * 64 + kk) * 128 + (o - 128)];
        }
        g_B3[id] = __float2bfloat16(v);
    } else if (id < 524288) {                  // B4 [8][256][128]
        int t = id - 262144, n = t >> 15, r = t & 32767, k = r >> 7, o = r & 127;
        float v;
        if (k < 128)
            v = (o < 64) ? w2[((size_t)n * 128 + k) * 64 + o]
                         : w2[((size_t)(8 + n) * 128 + k) * 64 + (o - 64)];
        else {
            int kk = k - 128;
            v = (o < 64) ? -w2[((size_t)(8 + n) * 128 + kk) * 64 + o]
                         : w2[((size_t)n * 128 + kk) * 64 + (o - 64)];
        }
        g_B4[t] = __float2bfloat16(v);
    } else if (id < 526336) {                  // b3f [8][256]
        int t = id - 524288, n = t >> 8, o = t & 255;
        g_b3f[t] = (o < 128) ? b1[n * 128 + o] : b1[1024 + n * 128 + (o - 128)];
    } else if (id < 527360) {                  // b4f [8][128]
        int t = id - 526336, n = t >> 7, o = t & 127;
        g_b4f[t] = (o < 64) ? b2[n * 64 + o] : b2[512 + n * 64 + (o - 64)];
    }
}

// ---------------------------------------------------------------------------
// S1: Y[b][m=ri*64+ky][wc] = A1 @ x
__global__ __launch_bounds__(256) void k_s1(const float* __restrict__ x) {
    GEMM_PROLOG
    const int col0 = blockIdx.x * 64, b = blockIdx.y;
    const float* xb = x + (size_t)b * HDIM * N1;
    for (int kt = 0; kt < 4; kt++) {
        lda_tile(g_A1 + kt * 64, 256, As, tid);
        ldb_tile_f32(xb + (size_t)(kt * 64) * N1 + col0, N1, Bs, tid);
        __syncthreads();
        compute_tile(As, Bs, acc, lane, wm, wn);
        __syncthreads();
    }
    size_t base = ((size_t)b * 128) * N1 + col0;
#pragma unroll
    for (int fm = 0; fm < 2; fm++)
#pragma unroll
        for (int fn = 0; fn < 4; fn++) {
            int m = wm * 32 + fm * 16 + (lane >> 2);
            int col = wn * 32 + fn * 8 + ((lane & 3) << 1);
            const float* d = acc[fm][fn];
#pragma unroll
            for (int hh = 0; hh < 2; hh++) {
                size_t idx = base + (size_t)(m + hh * 8) * N1 + col;
                *(unsigned*)&g_Y[idx] = pack_bf16(d[hh * 2], d[hh * 2 + 1]);
            }
        }
}

// S2: per slab (b,ky): Z = A2 @ [Yr;Yi]
__global__ __launch_bounds__(256) void k_s2() {
    GEMM_PROLOG
    const int bx = blockIdx.x, slab = blockIdx.y;
    const int b = slab >> 6, ky = slab & 63;
    const int c0 = bx * 64;
    for (int kt = 0; kt < 8; kt++) {
        lda_tile(g_A2 + kt * 64, 512, As, tid);
        int ri = kt >> 2, w0 = (kt & 3) * 64;
        ldb_tile_bf16(g_Y + ((size_t)b * 128 + ri * 64 + ky) * N1 + (size_t)w0 * 512 + c0,
                      512, Bs, tid);
        __syncthreads();
        compute_tile(As, Bs, acc, lane, wm, wn);
        __syncthreads();
    }
    size_t pbase = (size_t)slab * 64;
#pragma unroll
    for (int fm = 0; fm < 2; fm++)
#pragma unroll
        for (int fn = 0; fn < 4; fn++) {
            int m = wm * 32 + fm * 16 + (lane >> 2);
            int col = wn * 32 + fn * 8 + ((lane & 3) << 1);
            const float* d = acc[fm][fn];
#pragma unroll
            for (int hh = 0; hh < 2; hh++) {
                int mm = m + hh * 8;
                int ri = mm >> 6, kx = mm & 63;
                size_t idx = (pbase + kx) * 1024 + (size_t)bx * 128 + ri * 64 + col;
                *(unsigned*)&g_Z[idx] = pack_bf16(d[hh * 2], d[hh * 2 + 1]);
            }
        }
}

// S3a: H = gelu(Z @ B3 + b3)
__global__ __launch_bounds__(256) void k_s3a() {
    GEMM_PROLOG
    const int p0 = blockIdx.x * 128, o0 = blockIdx.y * 64, n = blockIdx.z;
    for (int kt = 0; kt < 2; kt++) {
        lda_tile(g_Z + (size_t)p0 * 1024 + n * 128 + kt * 64, 1024, As, tid);
        ldb_tile_bf16(g_B3 + ((size_t)n * 128 + kt * 64) * 256 + o0, 256, Bs, tid);
        __syncthreads();
        compute_tile(As, Bs, acc, lane, wm, wn);
        __syncthreads();
    }
#pragma unroll
    for (int fm = 0; fm < 2; fm++)
#pragma unroll
        for (int fn = 0; fn < 4; fn++) {
            int m = wm * 32 + fm * 16 + (lane >> 2);
            int o2 = o0 + wn * 32 + fn * 8 + ((lane & 3) << 1);
            float2 bv = *(const float2*)&g_b3f[n * 256 + o2];
            const float* d = acc[fm][fn];
#pragma unroll
            for (int hh = 0; hh < 2; hh++) {
                int p = p0 + m + hh * 8;
                size_t idx = (size_t)p * 2048 + n * 256 + o2;
                *(unsigned*)&g_H[idx] =
                    pack_bf16(gelu_f(d[hh * 2] + bv.x), gelu_f(d[hh * 2 + 1] + bv.y));
            }
        }
}

// S3b: O = H @ B4 + b4
__global__ __launch_bounds__(256) void k_s3b() {
    GEMM_PROLOG
    const int p0 = blockIdx.x * 128, o0 = blockIdx.y * 64, n = blockIdx.z;
    for (int kt = 0; kt < 4; kt++) {
        lda_tile(g_H + (size_t)p0 * 2048 + n * 256 + kt * 64, 2048, As, tid);
        ldb_tile_bf16(g_B4 + ((size_t)n * 256 + kt * 64) * 128 + o0, 128, Bs, tid);
        __syncthreads();
        compute_tile(As, Bs, acc, lane, wm, wn);
        __syncthreads();
    }
#pragma unroll
    for (int fm = 0; fm < 2; fm++)
#pragma unroll
        for (int fn = 0; fn < 4; fn++) {
            int m = wm * 32 + fm * 16 + (lane >> 2);
            int o2 = o0 + wn * 32 + fn * 8 + ((lane & 3) << 1);
            float2 bv = *(const float2*)&g_b4f[n * 128 + o2];
            int ri = o2 >> 6, c = n * 64 + (o2 & 63);
            const float* d = acc[fm][fn];
#pragma unroll
            for (int hh = 0; hh < 2; hh++) {
                int p = p0 + m + hh * 8;
                int b = p >> 12, ky = (p >> 6) & 63, kx = p & 63;
                size_t idx = (((size_t)(b * 64 + ky) * 2 + ri) * 64 + kx) * 512 + c;
                *(unsigned*)&g_O[idx] =
                    pack_bf16(d[hh * 2] + bv.x, d[hh * 2 + 1] + bv.y);
            }
        }
}

// S4: per slab: [Ur;Ui] = A4 @ [Or;Oi]
__global__ __launch_bounds__(256) void k_s4() {
    GEMM_PROLOG
    const int c0 = blockIdx.x * 64, m0 = blockIdx.y * 128, slab = blockIdx.z;
    const int b = slab >> 6, ky = slab & 63;
    for (int kt = 0; kt < 2; kt++) {
        lda_tile(g_A4 + (size_t)m0 * 128 + kt * 64, 128, As, tid);
        ldb_tile_bf16(g_O + ((size_t)(slab * 2 + kt)) * 64 * 512 + c0, 512, Bs, tid);
        __syncthreads();
        compute_tile(As, Bs, acc, lane, wm, wn);
        __syncthreads();
    }
#pragma unroll
    for (int fm = 0; fm < 2; fm++)
#pragma unroll
        for (int fn = 0; fn < 4; fn++) {
            int m = wm * 32 + fm * 16 + (lane >> 2);
            int c = c0 + wn * 32 + fn * 8 + ((lane & 3) << 1);
            const float* d = acc[fm][fn];
#pragma unroll
            for (int hh = 0; hh < 2; hh++) {
                int mg = m0 + m + hh * 8;
                size_t row, w;
                if (mg < 256) { row = (size_t)b * 128 + ky;      w = mg; }
                else          { row = (size_t)b * 128 + 64 + ky; w = mg - 256; }
                size_t idx = row * N1 + w * 512 + c;
                *(unsigned*)&g_U[idx] = pack_bf16(d[hh * 2], d[hh * 2 + 1]);
            }
        }
}

// S5: out = x + A5 @ [Ur;Ui]
__global__ __launch_bounds__(256) void k_s5(const float* __restrict__ x,
                                            float* __restrict__ out) {
    GEMM_PROLOG
    const int col0 = blockIdx.x * 64, m0 = blockIdx.y * 128, b = blockIdx.z;
    for (int kt = 0; kt < 2; kt++) {
        lda_tile(g_A5 + (size_t)m0 * 128 + kt * 64, 128, As, tid);
        ldb_tile_bf16(g_U + ((size_t)b * 128 + kt * 64) * N1 + col0, N1, Bs, tid);
        __syncthreads();
        compute_tile(As, Bs, acc, lane, wm, wn);
        __syncthreads();
    }
#pragma unroll
    for (int fm = 0; fm < 2; fm++)
#pragma unroll
        for (int fn = 0; fn < 4; fn++) {
            int m = wm * 32 + fm * 16 + (lane >> 2);
            int col = wn * 32 + fn * 8 + ((lane & 3) << 1);
            const float* d = acc[fm][fn];
#pragma unroll
            for (int hh = 0; hh < 2; hh++) {
                int h = m0 + m + hh * 8;
                size_t idx = ((size_t)b * HDIM + h) * N1 + col0 + col;
                float2 xv = *(const float2*)&x[idx];
                float2 o;
                o.x = xv.x + d[hh * 2];
                o.y = xv.y + d[hh * 2 + 1];
                *(float2*)&out[idx] = o;
            }
        }
}

// ---------------------------------------------------------------------------
extern "C" void kernel_launch(void* const* d_in, const int* in_sizes, int n_in,
                              void* d_out, int out_size) {
    const float* x  = (const float*)d_in[0];
    const float* w1 = (const float*)d_in[1];
    const float* b1 = (const float*)d_in[2];
    const float* w2 = (const float*)d_in[3];
    const float* b2 = (const float*)d_in[4];
    float* out = (float*)d_out;

    k_prep_dft<<<768, 256>>>();
    k_prep_w<<<2060, 256>>>(w1, b1, w2, b2);
    k_s1<<<dim3(N1 / 64, BATCH), 256>>>(x);
    k_s2<<<dim3(8, BATCH * KM), 256>>>();
    k_s3a<<<dim3(64, 4, NBLK), 256>>>();
    k_s3b<<<dim3(64, 2, NBLK), 256>>>();
    k_s4<<<dim3(8, 4, BATCH * KM), 256>>>();
    k_s5<<<dim3(N1 / 64, 2, BATCH), 256>>>(x, out);
}